// round 5
// baseline (speedup 1.0000x reference)
#include <cuda_runtime.h>

#define NT 128
#define PI_F 3.14159265358979323846f

// ---------- packed f32x2 primitives ----------
struct P2 { union { float2 f; unsigned long long u; }; };

__device__ __forceinline__ P2 mk2(float a, float b) { P2 p; p.f.x = a; p.f.y = b; return p; }
__device__ __forceinline__ P2 dup2(float a) { return mk2(a, a); }

__device__ __forceinline__ P2 fma2(P2 a, P2 b, P2 c) {
    P2 d;
    asm("fma.rn.f32x2 %0, %1, %2, %3;" : "=l"(d.u) : "l"(a.u), "l"(b.u), "l"(c.u));
    return d;
}
__device__ __forceinline__ P2 mul2(P2 a, P2 b) {
    P2 d;
    asm("mul.rn.f32x2 %0, %1, %2;" : "=l"(d.u) : "l"(a.u), "l"(b.u));
    return d;
}
__device__ __forceinline__ P2 relu2(P2 a) { P2 d; d.f.x = fmaxf(a.f.x, 0.f); d.f.y = fmaxf(a.f.y, 0.f); return d; }

// Bloch-sphere / Pauli-string collapsed quantum encoder for one lane-packed row pair.
__device__ __forceinline__ void compute_zv(const float xsA[8], const float xsB[8],
                                           const float2* __restrict__ sK, P2 zv[4])
{
    P2 X[4], Y[4], Z[4];
#pragma unroll
    for (int i = 0; i < 4; i++) {
        float saA, caA, sbA, cbA, saB, caB, sbB, cbB;
        __sincosf(xsA[i]     * PI_F, &saA, &caA);
        __sincosf(xsA[i + 4] * PI_F, &sbA, &cbA);
        __sincosf(xsB[i]     * PI_F, &saB, &caB);
        __sincosf(xsB[i + 4] * PI_F, &sbB, &cbB);
        P2 sa = mk2(saA, saB), sb = mk2(sbA, sbB), cb = mk2(cbA, cbB);
        X[i] = mul2(sa, cb);
        Y[i] = mul2(sa, sb);
        Z[i] = mk2(caA, caB);
    }

    P2 A  = mul2(X[0], X[1]);
    P2 B  = mul2(Y[0], Y[1]);
    P2 F  = mul2(X[1], X[2]);
    P2 H  = mul2(X[0], X[2]);
    P2 D  = mul2(X[2], X[3]);
    P2 E  = mul2(Y[2], Y[3]);
    P2 G  = mul2(Y[1], Y[2]);
    P2 ZF = mul2(Z[0], F);
    P2 Z0Z2 = mul2(Z[0], Z[2]);
    P2 YZ   = mul2(Y[0], Z[1]);
    P2 YZY  = mul2(YZ, Y[2]);

#define KLD(n) ({ P2 _k; _k.f = sK[n]; _k; })

    P2 z0 = mul2(KLD(0), Z[0]);
    z0 = fma2(KLD(1), A, z0);

    P2 z1 = mul2(KLD(2), Z[1]);
    z1 = fma2(KLD(3), ZF, z1);
    z1 = fma2(KLD(4), B, z1);
    z1 = fma2(KLD(5), H, z1);

    P2 Z1D   = mul2(Z[1], D);
    P2 X1X3  = mul2(X[1], X[3]);
    P2 ZX1X3 = mul2(Z[0], X1X3);
    P2 AZ2   = mul2(A, Z[2]);
    P2 BD    = mul2(B, D);
    P2 X0X3  = mul2(X[0], X[3]);
    P2 z2 = mul2(KLD(6), Z0Z2);
    z2 = fma2(KLD(7),  Z1D,   z2);
    z2 = fma2(KLD(8),  G,     z2);
    z2 = fma2(KLD(9),  ZX1X3, z2);
    z2 = fma2(KLD(10), AZ2,   z2);
    z2 = fma2(KLD(11), BD,    z2);
    z2 = fma2(KLD(12), YZY,   z2);
    z2 = fma2(KLD(13), X0X3,  z2);

    P2 Z1Z3 = mul2(Z[1], Z[3]);
    P2 BZ3  = mul2(B, Z[3]);
    P2 ZF3  = mul2(ZF, Z[3]);
    P2 Z0E  = mul2(Z[0], E);
    P2 ZZX  = mul2(Z0Z2, X[3]);
    P2 HZ3  = mul2(H, Z[3]);
    P2 AE   = mul2(A, E);
    P2 AZX  = mul2(AZ2, X[3]);
    P2 Y1Z2 = mul2(Y[1], Z[2]);
    P2 YZ2Y3 = mul2(Y1Z2, Y[3]);
    P2 GX3  = mul2(G, X[3]);
    P2 Z1X2 = mul2(Z[1], X[2]);
    P2 YZZ  = mul2(YZ, Z[2]);
    P2 YZZY = mul2(YZZ, Y[3]);
    P2 YZYX = mul2(YZY, X[3]);
    P2 BX2  = mul2(B, X[2]);
    P2 Z0X1 = mul2(Z[0], X[1]);
    P2 z3 = mul2(KLD(14), Z1Z3);
    z3 = fma2(KLD(15), BZ3,   z3);
    z3 = fma2(KLD(16), ZF3,   z3);
    z3 = fma2(KLD(17), Z0E,   z3);
    z3 = fma2(KLD(18), ZZX,   z3);
    z3 = fma2(KLD(19), HZ3,   z3);
    z3 = fma2(KLD(20), AE,    z3);
    z3 = fma2(KLD(21), AZX,   z3);
    z3 = fma2(KLD(22), YZ2Y3, z3);
    z3 = fma2(KLD(23), GX3,   z3);
    z3 = fma2(KLD(24), Z1X2,  z3);
    z3 = fma2(KLD(25), YZZY,  z3);
    z3 = fma2(KLD(26), YZYX,  z3);
    z3 = fma2(KLD(27), BX2,   z3);
    z3 = fma2(KLD(28), Z0X1,  z3);
    z3 = fma2(KLD(29), X[0],  z3);

    zv[0] = z0; zv[1] = z1; zv[2] = z2; zv[3] = z3;
}

__global__ void __launch_bounds__(NT)
qae5_kernel(const float* __restrict__ x,
            const float* __restrict__ qw,
            const float* __restrict__ W1, const float* __restrict__ b1,
            const float* __restrict__ W2, const float* __restrict__ b2,
            const float* __restrict__ W3, const float* __restrict__ b3,
            float* __restrict__ out, int nrows)
{
    __shared__ __align__(16) float2 sW1[32];
    __shared__ __align__(16) float2 sW2[256];
    __shared__ __align__(16) float2 sW3[256];
    __shared__ __align__(16) float2 sb1[8];
    __shared__ __align__(16) float2 sb2[16];
    __shared__ __align__(16) float2 sb3[8];
    __shared__ __align__(8)  float2 sK[30];

    const int tid = threadIdx.x;
    for (int i = tid; i < 32; i += NT) {
        int p = i >> 2, k = i & 3;
        sW1[i] = make_float2(W1[(2 * p) * 4 + k], W1[(2 * p + 1) * 4 + k]);
    }
    for (int i = tid; i < 256; i += NT) {
        int p2 = i >> 4, k2 = i & 15;
        sW2[i] = make_float2(W2[(2 * p2) * 16 + k2], W2[(2 * p2 + 1) * 16 + k2]);
        int p3 = i >> 5, k3 = i & 31;
        sW3[i] = make_float2(W3[(2 * p3) * 32 + k3], W3[(2 * p3 + 1) * 32 + k3]);
    }
    if (tid < 8)  sb1[tid] = make_float2(b1[2 * tid], b1[2 * tid + 1]);
    if (tid < 16) sb2[tid] = make_float2(b2[2 * tid], b2[2 * tid + 1]);
    if (tid < 8)  sb3[tid] = make_float2(b3[2 * tid], b3[2 * tid + 1]);
    if (tid == 0) {
        float c[4], s[4];
#pragma unroll
        for (int i = 0; i < 4; i++) __sincosf(qw[2 * i], &s[i], &c[i]);
        float kv[30];
        kv[0]  =  c[0];                    kv[1]  = -s[0];
        kv[2]  =  c[0] * c[1];             kv[3]  = -c[0] * s[1];
        kv[4]  =  s[0] * c[1];             kv[5]  =  s[0] * s[1];
        kv[6]  =  c[0] * c[1] * c[2];      kv[7]  = -c[0] * c[1] * s[2];
        kv[8]  =  c[0] * s[1] * c[2];      kv[9]  =  c[0] * s[1] * s[2];
        kv[10] = -s[0] * c[1] * c[2];      kv[11] = -s[0] * c[1] * s[2];
        kv[12] = -s[0] * s[1] * c[2];      kv[13] = -s[0] * s[1] * s[2];
        kv[14] =  c[0] * c[1] * c[2] * c[3];
        kv[15] =  s[0] * c[1] * c[2] * c[3];
        kv[16] = -c[0] * s[1] * c[2] * c[3];
        kv[17] =  c[0] * c[1] * s[2] * c[3];
        kv[18] = -c[0] * c[1] * c[2] * s[3];
        kv[19] =  s[0] * s[1] * c[2] * c[3];
        kv[20] = -s[0] * c[1] * s[2] * c[3];
        kv[21] =  s[0] * c[1] * c[2] * s[3];
        kv[22] = -c[0] * s[1] * s[2] * c[3];
        kv[23] = -c[0] * s[1] * c[2] * s[3];
        kv[24] =  c[0] * c[1] * s[2] * s[3];
        kv[25] =  s[0] * s[1] * s[2] * c[3];
        kv[26] =  s[0] * s[1] * c[2] * s[3];
        kv[27] =  s[0] * c[1] * s[2] * s[3];
        kv[28] = -c[0] * s[1] * s[2] * s[3];
        kv[29] =  s[0] * s[1] * s[2] * s[3];
#pragma unroll
        for (int i = 0; i < 30; i++) sK[i] = make_float2(kv[i], kv[i]);
    }
    __syncthreads();

    // 4 rows per thread: r[s] = base + s*NT
    const int base = blockIdx.x * (NT * 4) + tid;
    if (base >= nrows) return;
    int r[4];
#pragma unroll
    for (int s = 0; s < 4; s++) {
        int rr = base + s * NT;
        r[s] = (rr < nrows) ? rr : base;   // clamp reads; stores guarded below
    }

    // ---- load features (front-batched LDG) ----
    float4 f0[4], f1[4];
#pragma unroll
    for (int s = 0; s < 4; s++) {
        const float4* xp = reinterpret_cast<const float4*>(x + (size_t)r[s] * 16);
        f0[s] = xp[0]; f1[s] = xp[1];
    }

    // ---- quantum encoder, two lane-packed row pairs ----
    P2 zv0[4], zv1[4];
    {
        float xsA[8] = {f0[0].x, f0[0].y, f0[0].z, f0[0].w, f1[0].x, f1[0].y, f1[0].z, f1[0].w};
        float xsB[8] = {f0[1].x, f0[1].y, f0[1].z, f0[1].w, f1[1].x, f1[1].y, f1[1].z, f1[1].w};
        compute_zv(xsA, xsB, sK, zv0);
    }
    {
        float xsA[8] = {f0[2].x, f0[2].y, f0[2].z, f0[2].w, f1[2].x, f1[2].y, f1[2].z, f1[2].w};
        float xsB[8] = {f0[3].x, f0[3].y, f0[3].z, f0[3].w, f1[3].x, f1[3].y, f1[3].z, f1[3].w};
        compute_zv(xsA, xsB, sK, zv1);
    }

    // ---- dup'd z inputs per row: row0=zv0.x row1=zv0.y row2=zv1.x row3=zv1.y ----
    P2 zd[4][4];
#pragma unroll
    for (int k = 0; k < 4; k++) {
        zd[0][k] = dup2(zv0[k].f.x);
        zd[1][k] = dup2(zv0[k].f.y);
        zd[2][k] = dup2(zv1[k].f.x);
        zd[3][k] = dup2(zv1[k].f.y);
    }

    // ---- Layer 1: 4 -> 16 ; weights loaded once, used by 4 rows ----
    float h1s[4][16];
#pragma unroll
    for (int pp = 0; pp < 8; pp++) {
        const float4* wp = reinterpret_cast<const float4*>(sW1 + pp * 4);
        float4 w0 = wp[0], w1 = wp[1];
        P2 wk0 = mk2(w0.x, w0.y), wk1 = mk2(w0.z, w0.w);
        P2 wk2 = mk2(w1.x, w1.y), wk3 = mk2(w1.z, w1.w);
        P2 bias; bias.f = sb1[pp];
#pragma unroll
        for (int s = 0; s < 4; s++) {
            P2 acc = bias;
            acc = fma2(wk0, zd[s][0], acc);
            acc = fma2(wk1, zd[s][1], acc);
            acc = fma2(wk2, zd[s][2], acc);
            acc = fma2(wk3, zd[s][3], acc);
            acc = relu2(acc);
            h1s[s][2 * pp] = acc.f.x;
            h1s[s][2 * pp + 1] = acc.f.y;
        }
    }

    // ---- Layer 2: 16 -> 32 ; k-chunks of 2, dups hoisted per chunk ----
    P2 acc2[4][16];
#pragma unroll
    for (int pp = 0; pp < 16; pp++) {
        P2 bias; bias.f = sb2[pp];
#pragma unroll
        for (int s = 0; s < 4; s++) acc2[s][pp] = bias;
    }
#pragma unroll
    for (int ch = 0; ch < 8; ch++) {
        P2 hd[4][2];
#pragma unroll
        for (int s = 0; s < 4; s++) {
            hd[s][0] = dup2(h1s[s][ch * 2]);
            hd[s][1] = dup2(h1s[s][ch * 2 + 1]);
        }
#pragma unroll
        for (int pp = 0; pp < 16; pp++) {
            float4 w = *reinterpret_cast<const float4*>(sW2 + pp * 16 + ch * 2);
            P2 wa = mk2(w.x, w.y), wb = mk2(w.z, w.w);
#pragma unroll
            for (int s = 0; s < 4; s++) {
                acc2[s][pp] = fma2(wa, hd[s][0], acc2[s][pp]);
                acc2[s][pp] = fma2(wb, hd[s][1], acc2[s][pp]);
            }
        }
    }
#pragma unroll
    for (int pp = 0; pp < 16; pp++)
#pragma unroll
        for (int s = 0; s < 4; s++) acc2[s][pp] = relu2(acc2[s][pp]);

    // ---- Layer 3: 32 -> 16 ; k-chunks of 2 ----
    P2 acc3[4][8];
#pragma unroll
    for (int qq = 0; qq < 8; qq++) {
        P2 bias; bias.f = sb3[qq];
#pragma unroll
        for (int s = 0; s < 4; s++) acc3[s][qq] = bias;
    }
#pragma unroll
    for (int ch = 0; ch < 16; ch++) {
        P2 hd[4][2];
#pragma unroll
        for (int s = 0; s < 4; s++) {
            int k0 = ch * 2, k1 = ch * 2 + 1;
            float v0 = (k0 & 1) ? acc2[s][k0 >> 1].f.y : acc2[s][k0 >> 1].f.x;
            float v1 = (k1 & 1) ? acc2[s][k1 >> 1].f.y : acc2[s][k1 >> 1].f.x;
            hd[s][0] = dup2(v0);
            hd[s][1] = dup2(v1);
        }
#pragma unroll
        for (int qq = 0; qq < 8; qq++) {
            float4 w = *reinterpret_cast<const float4*>(sW3 + qq * 32 + ch * 2);
            P2 wa = mk2(w.x, w.y), wb = mk2(w.z, w.w);
#pragma unroll
            for (int s = 0; s < 4; s++) {
                acc3[s][qq] = fma2(wa, hd[s][0], acc3[s][qq]);
                acc3[s][qq] = fma2(wb, hd[s][1], acc3[s][qq]);
            }
        }
    }

    // ---- stores ----
#pragma unroll
    for (int s = 0; s < 4; s++) {
        int rr = base + s * NT;
        if (rr < nrows) {
            float4* op = reinterpret_cast<float4*>(out + (size_t)rr * 16);
#pragma unroll
            for (int q = 0; q < 4; q++)
                op[q] = make_float4(acc3[s][2 * q].f.x, acc3[s][2 * q].f.y,
                                    acc3[s][2 * q + 1].f.x, acc3[s][2 * q + 1].f.y);
        }
    }
}

extern "C" void kernel_launch(void* const* d_in, const int* in_sizes, int n_in,
                              void* d_out, int out_size) {
    const float* x  = (const float*)d_in[0];
    const float* qw = (const float*)d_in[1];
    const float* W1 = (const float*)d_in[2];
    const float* b1 = (const float*)d_in[3];
    const float* W2 = (const float*)d_in[4];
    const float* b2 = (const float*)d_in[5];
    const float* W3 = (const float*)d_in[6];
    const float* b3 = (const float*)d_in[7];
    float* out = (float*)d_out;

    int nrows = in_sizes[0] / 16;
    int grid = (nrows + NT * 4 - 1) / (NT * 4);
    qae5_kernel<<<grid, NT>>>(x, qw, W1, b1, W2, b2, W3, b3, out, nrows);
}